// round 1
// baseline (speedup 1.0000x reference)
#include <cuda_runtime.h>
#include <cuda_bf16.h>
#include <math.h>

#define T 64
#define B 128
#define H 64
#define L 64
#define NPART 2          // column-split per layer
#define KMAX 128         // concat(x_in, h) padded
#define NCOLS 128        // 4 gates * 32 h-cols per part

// Scratch: h history [layer][time][batch][h]  (128 MB) + ready flags
__device__ float g_h[L][T][B][H];
__device__ int   g_flag[L * T];

__device__ __forceinline__ float sigf(float v) {
    return 1.0f / (1.0f + __expf(-v));
}

__global__ void reset_kernel() {
    int i = blockIdx.x * blockDim.x + threadIdx.x;
    if (i < L * T) g_flag[i] = 0;
}

// 128 CTAs: blockIdx.x = l*NPART + p.  256 threads.
// Each CTA computes z[B=128, 128 interleaved gate cols] = X[128,K] @ Wslice[K,128]
// Wslice col c = j*4+g maps to global W col g*64 + p*32 + j.
__global__ void __launch_bounds__(256, 1)
lstm_wavefront_kernel(const float* __restrict__ x,
                      const float* __restrict__ W0,
                      const float* __restrict__ b0,
                      const float* __restrict__ Wl,
                      const float* __restrict__ bl) {
    extern __shared__ float smem[];
    float* Ws = smem;                 // [KMAX][NCOLS]  64 KB
    float* Xs = smem + KMAX * NCOLS;  // [KMAX][B]      64 KB (transposed X)

    const int l = blockIdx.x / NPART;
    const int p = blockIdx.x % NPART;
    const int tid = threadIdx.x;
    const int rt = tid >> 4;          // 0..15 row tile
    const int ct = tid & 15;          // 0..15 col tile
    const int r0 = rt * 8;
    const int j0 = ct * 2;            // h-column offset within this part (2 per thread)

    // ---- load weight slice once (reused for all 64 timesteps) ----
    if (l == 0) {
        for (int idx = tid; idx < KMAX * NCOLS; idx += 256) {
            int k = idx >> 7, c = idx & 127;
            int j = c >> 2, g = c & 3;
            Ws[idx] = (k < 65) ? W0[k * 256 + g * 64 + p * 32 + j] : 0.0f;
        }
        // zero the padded X rows once (never rewritten for l==0)
        for (int idx = 65 * B + tid; idx < KMAX * B; idx += 256) Xs[idx] = 0.0f;
    } else {
        const float* W = Wl + (size_t)(l - 1) * 128 * 256;
        for (int idx = tid; idx < KMAX * NCOLS; idx += 256) {
            int k = idx >> 7, c = idx & 127;
            int j = c >> 2, g = c & 3;
            Ws[idx] = W[k * 256 + g * 64 + p * 32 + j];
        }
    }

    // biases for this thread's 2 h-cols x 4 gates
    const float* bptr = (l == 0) ? b0 : (bl + (size_t)(l - 1) * 256);
    float bias[2][4];
#pragma unroll
    for (int jj = 0; jj < 2; ++jj)
#pragma unroll
        for (int g = 0; g < 4; ++g)
            bias[jj][g] = bptr[g * 64 + p * 32 + j0 + jj];

    float cst[8][2];
#pragma unroll
    for (int i = 0; i < 8; ++i) { cst[i][0] = 0.0f; cst[i][1] = 0.0f; }

    const int kmax = (l == 0) ? 68 : 128;   // layer 0: K=65 padded to /4

    for (int t = 0; t < T; ++t) {
        // ---- wait for producers (dataflow; no global barrier) ----
        __syncthreads();   // also protects Xs reuse from previous epilogue
        if (tid == 0) {
            if (l > 0) {
                volatile int* f = &g_flag[(l - 1) * T + t];
                while (*f < NPART) { }
            }
            if (t > 0) {
                volatile int* f = &g_flag[l * T + (t - 1)];
                while (*f < NPART) { }
            }
            __threadfence();   // acquire
        }
        __syncthreads();

        // ---- stage X (transposed: Xs[k][b]) ----
        if (l == 0) {
            for (int b = tid; b < B; b += 256) Xs[b] = x[b * T + t];
            for (int idx = tid; idx < 64 * B; idx += 256) {
                int k = idx >> 7, b = idx & 127;
                Xs[(k + 1) * B + b] = (t == 0) ? 0.0f : g_h[0][t - 1][b][k];
            }
        } else {
            for (int idx = tid; idx < 64 * B; idx += 256) {
                int k = idx >> 7, b = idx & 127;
                Xs[k * B + b] = g_h[l - 1][t][b][k];
            }
            for (int idx = tid; idx < 64 * B; idx += 256) {
                int k = idx >> 7, b = idx & 127;
                Xs[(k + 64) * B + b] = (t == 0) ? 0.0f : g_h[l][t - 1][b][k];
            }
        }
        __syncthreads();

        // ---- GEMM: 8x8 register tile per thread ----
        float acc[8][8];
#pragma unroll
        for (int i = 0; i < 8; ++i)
#pragma unroll
            for (int j = 0; j < 8; ++j) acc[i][j] = 0.0f;

        const float4* Xs4 = (const float4*)Xs;
        const float4* Ws4 = (const float4*)Ws;
#pragma unroll 4
        for (int k = 0; k < kmax; ++k) {
            float4 xa = Xs4[k * 32 + rt * 2];
            float4 xb = Xs4[k * 32 + rt * 2 + 1];
            float4 wa = Ws4[k * 32 + ct * 2];
            float4 wb = Ws4[k * 32 + ct * 2 + 1];
            float xr[8] = {xa.x, xa.y, xa.z, xa.w, xb.x, xb.y, xb.z, xb.w};
            float wc[8] = {wa.x, wa.y, wa.z, wa.w, wb.x, wb.y, wb.z, wb.w};
#pragma unroll
            for (int i = 0; i < 8; ++i)
#pragma unroll
                for (int j = 0; j < 8; ++j)
                    acc[i][j] = fmaf(xr[i], wc[j], acc[i][j]);
        }

        // ---- gates + state update; stage h into smem (reuse Xs front) ----
        __syncthreads();   // everyone done reading Xs before overwrite
#pragma unroll
        for (int i = 0; i < 8; ++i) {
            int b = r0 + i;
#pragma unroll
            for (int jj = 0; jj < 2; ++jj) {
                float zi = acc[i][jj * 4 + 0] + bias[jj][0];
                float zj = acc[i][jj * 4 + 1] + bias[jj][1];
                float zf = acc[i][jj * 4 + 2] + bias[jj][2];
                float zo = acc[i][jj * 4 + 3] + bias[jj][3];
                float c2 = cst[i][jj] * sigf(zf) + sigf(zi) * tanhf(zj);
                float h2 = tanhf(c2) * sigf(zo);
                cst[i][jj] = c2;
                Xs[b * 32 + j0 + jj] = h2;   // Hs[b][j], 16 KB staging
            }
        }
        __syncthreads();

        // ---- coalesced h writeback + release ----
        for (int idx = tid; idx < B * 8; idx += 256) {
            int b = idx >> 3, q = idx & 7;
            ((float4*)&g_h[l][t][b][p * 32])[q] = ((const float4*)&Xs[b * 32])[q];
        }
        __threadfence();   // release: make stores visible before flag
        __syncthreads();
        if (tid == 0) atomicAdd(&g_flag[l * T + t], 1);
    }
}

// pred[b,t] = relu(h_top[t,b,:] . Wd[t] + bd[t]);  loss = mean((labels-pred)^2)
__global__ void dense_loss_kernel(const float* __restrict__ labels,
                                  const float* __restrict__ Wd,
                                  const float* __restrict__ bd,
                                  float* __restrict__ out, int out_size) {
    __shared__ float red[256];
    const int tid = threadIdx.x;
    float lsum = 0.0f;
    for (int idx = tid; idx < B * T; idx += 256) {
        int b = idx >> 6, t = idx & 63;
        const float4* h = (const float4*)&g_h[L - 1][t][b][0];
        const float4* w = (const float4*)&Wd[t * H];
        float s = 0.0f;
#pragma unroll
        for (int q = 0; q < 16; ++q) {
            float4 hv = h[q], wv = w[q];
            s += hv.x * wv.x + hv.y * wv.y + hv.z * wv.z + hv.w * wv.w;
        }
        s += bd[t];
        float pred = fmaxf(s, 0.0f);
        if (out_size >= B * T) out[b * T + t] = pred;
        float d = labels[b * T + t] - pred;
        lsum += d * d;
    }
    red[tid] = lsum;
    __syncthreads();
    for (int s = 128; s > 0; s >>= 1) {
        if (tid < s) red[tid] += red[tid + s];
        __syncthreads();
    }
    if (tid == 0) {
        float loss = red[0] / (float)(B * T);
        if (out_size == B * T + 1) out[B * T] = loss;
        else if (out_size == 1) out[0] = loss;
    }
}

extern "C" void kernel_launch(void* const* d_in, const int* in_sizes, int n_in,
                              void* d_out, int out_size) {
    const float* x      = (const float*)d_in[0];
    const float* labels = (const float*)d_in[1];
    const float* W0     = (const float*)d_in[2];
    const float* b0     = (const float*)d_in[3];
    const float* Wl     = (const float*)d_in[4];
    const float* bl     = (const float*)d_in[5];
    const float* Wd     = (const float*)d_in[6];
    const float* bd     = (const float*)d_in[7];
    float* out = (float*)d_out;

    const int smem_bytes = 2 * KMAX * NCOLS * (int)sizeof(float);  // 128 KB
    cudaFuncSetAttribute(lstm_wavefront_kernel,
                         cudaFuncAttributeMaxDynamicSharedMemorySize, smem_bytes);

    reset_kernel<<<(L * T + 255) / 256, 256>>>();
    lstm_wavefront_kernel<<<L * NPART, 256, smem_bytes>>>(x, W0, b0, Wl, bl);
    dense_loss_kernel<<<1, 256>>>(labels, Wd, bd, out, out_size);
}

// round 2
// speedup vs baseline: 1.5458x; 1.5458x over previous
#include <cuda_runtime.h>
#include <cuda_bf16.h>
#include <math.h>

#define T 64
#define B 128
#define H 64
#define L 64
#define NPART 2          // column-split per layer
#define KMAX 128         // concat(x_in, h) padded
#define NCOLS 128        // 4 gates * 32 h-cols per part

// Scratch: h history TRANSPOSED [layer][time][h][batch] for coalesced staging
__device__ float g_h[L][T][H][B];
__device__ int   g_flag[L * T];
__device__ float g_lpart[T];

typedef unsigned long long u64;

__device__ __forceinline__ u64 pack2(float a, float b) {
    u64 r;
    asm("mov.b64 %0, {%1, %2};" : "=l"(r)
        : "r"(__float_as_uint(a)), "r"(__float_as_uint(b)));
    return r;
}
__device__ __forceinline__ void unpack2(u64 v, float& a, float& b) {
    unsigned int x, y;
    asm("mov.b64 {%0, %1}, %2;" : "=r"(x), "=r"(y) : "l"(v));
    a = __uint_as_float(x); b = __uint_as_float(y);
}
__device__ __forceinline__ u64 fma2(u64 a, u64 b, u64 c) {
    u64 d;
    asm("fma.rn.f32x2 %0, %1, %2, %3;" : "=l"(d) : "l"(a), "l"(b), "l"(c));
    return d;
}
__device__ __forceinline__ float fex2(float x) {
    float r; asm("ex2.approx.f32 %0, %1;" : "=f"(r) : "f"(x)); return r;
}
__device__ __forceinline__ float frcp(float x) {
    float r; asm("rcp.approx.f32 %0, %1;" : "=f"(r) : "f"(x)); return r;
}
__device__ __forceinline__ float sigf(float v) {
    return frcp(1.0f + fex2(-1.4426950408889634f * v));
}
__device__ __forceinline__ float tanh_fast(float v) {
    return 2.0f * sigf(2.0f * v) - 1.0f;
}

__global__ void reset_kernel() {
    int i = blockIdx.x * blockDim.x + threadIdx.x;
    if (i < L * T) g_flag[i] = 0;
}

// 128 CTAs: blockIdx.x = l*NPART + p.  256 threads, 1 CTA/SM (persistent wavefront).
__global__ void __launch_bounds__(256, 1)
lstm_wavefront_kernel(const float* __restrict__ x,
                      const float* __restrict__ W0,
                      const float* __restrict__ b0,
                      const float* __restrict__ Wl,
                      const float* __restrict__ bl) {
    extern __shared__ float smem[];
    float* Ws  = smem;                 // [KMAX][NCOLS]  64 KB
    float* Xs  = smem + KMAX * NCOLS;  // [KMAX][B]      64 KB (transposed X)
    float* Hst = Xs;                   // h staging [B][33] (reuses Xs rows 0..32)

    const int l = blockIdx.x / NPART;
    const int p = blockIdx.x % NPART;
    const int tid = threadIdx.x;
    const int rt = tid >> 4;           // 0..15 row tile
    const int ct = tid & 15;           // 0..15 col tile
    const int r0 = rt * 8;
    const int j0 = ct * 2;             // h-col offset within this part (2 per thread)

    // ---- load weight slice once (col c = j*4+g -> global col g*64 + p*32 + j) ----
    if (l == 0) {
        for (int idx = tid; idx < KMAX * NCOLS; idx += 256) {
            int k = idx >> 7, c = idx & 127;
            int j = c >> 2, g = c & 3;
            Ws[idx] = (k < 65) ? W0[k * 256 + g * 64 + p * 32 + j] : 0.0f;
        }
        // zero padded X rows 65..127 once (never rewritten for l==0)
        for (int idx = 65 * B + tid; idx < KMAX * B; idx += 256) Xs[idx] = 0.0f;
    } else {
        const float* W = Wl + (size_t)(l - 1) * 128 * 256;
        for (int idx = tid; idx < KMAX * NCOLS; idx += 256) {
            int k = idx >> 7, c = idx & 127;
            int j = c >> 2, g = c & 3;
            Ws[idx] = W[k * 256 + g * 64 + p * 32 + j];
        }
    }

    const float* bptr = (l == 0) ? b0 : (bl + (size_t)(l - 1) * 256);
    float bias[2][4];
#pragma unroll
    for (int jj = 0; jj < 2; ++jj)
#pragma unroll
        for (int g = 0; g < 4; ++g)
            bias[jj][g] = bptr[g * 64 + p * 32 + j0 + jj];

    float cst[8][2];
#pragma unroll
    for (int i = 0; i < 8; ++i) { cst[i][0] = 0.0f; cst[i][1] = 0.0f; }

    const int kmax = (l == 0) ? 68 : 128;

    for (int t = 0; t < T; ++t) {
        // ---- wait for producers ----
        __syncthreads();
        if (tid == 0) {
            if (l > 0) {
                volatile int* f = &g_flag[(l - 1) * T + t];
                while (*f < NPART) { }
            }
            if (t > 0) {
                volatile int* f = &g_flag[l * T + (t - 1)];
                while (*f < NPART) { }
            }
            __threadfence();
        }
        __syncthreads();

        // ---- stage X (Xs[k][b]) — fully coalesced float4 copies ----
        if (l == 0) {
            for (int b = tid; b < B; b += 256) Xs[b] = x[b * T + t];
            if (t == 0) {
                for (int idx = tid; idx < 64 * B; idx += 256) Xs[B + idx] = 0.0f;
            } else {
                for (int idx = tid; idx < 64 * 32; idx += 256) {
                    int k = idx >> 5, bq = idx & 31;
                    ((float4*)&Xs[(k + 1) * B])[bq] =
                        *(const float4*)&g_h[0][t - 1][k][bq * 4];
                }
            }
        } else {
            for (int idx = tid; idx < 64 * 32; idx += 256) {
                int k = idx >> 5, bq = idx & 31;
                ((float4*)&Xs[k * B])[bq] =
                    *(const float4*)&g_h[l - 1][t][k][bq * 4];
            }
            if (t == 0) {
                for (int idx = tid; idx < 64 * B; idx += 256) Xs[64 * B + idx] = 0.0f;
            } else {
                for (int idx = tid; idx < 64 * 32; idx += 256) {
                    int k = idx >> 5, bq = idx & 31;
                    ((float4*)&Xs[(k + 64) * B])[bq] =
                        *(const float4*)&g_h[l][t - 1][k][bq * 4];
                }
            }
        }
        __syncthreads();

        // ---- GEMM: 8x8 tile via packed fma.rn.f32x2 (pairs along rows) ----
        u64 acc2[4][8];
#pragma unroll
        for (int i = 0; i < 4; ++i)
#pragma unroll
            for (int j = 0; j < 8; ++j) acc2[i][j] = 0ULL;

        const float4* Xs4 = (const float4*)Xs;
        const float4* Ws4 = (const float4*)Ws;
#pragma unroll 2
        for (int k = 0; k < kmax; ++k) {
            float4 xa = Xs4[k * 32 + rt * 2];
            float4 xb = Xs4[k * 32 + rt * 2 + 1];
            float4 wa = Ws4[k * 32 + ct * 2];
            float4 wb = Ws4[k * 32 + ct * 2 + 1];
            u64 xp[4];
            xp[0] = pack2(xa.x, xa.y); xp[1] = pack2(xa.z, xa.w);
            xp[2] = pack2(xb.x, xb.y); xp[3] = pack2(xb.z, xb.w);
            float wf[8] = {wa.x, wa.y, wa.z, wa.w, wb.x, wb.y, wb.z, wb.w};
            u64 wd[8];
#pragma unroll
            for (int j = 0; j < 8; ++j) wd[j] = pack2(wf[j], wf[j]);
#pragma unroll
            for (int ip = 0; ip < 4; ++ip)
#pragma unroll
                for (int j = 0; j < 8; ++j)
                    acc2[ip][j] = fma2(xp[ip], wd[j], acc2[ip][j]);
        }

        // ---- gates + state update; stage h into padded smem Hst[b][33] ----
        __syncthreads();   // all GEMM reads of Xs done before overwrite
#pragma unroll
        for (int ip = 0; ip < 4; ++ip) {
            float za[8], zb[8];   // rows r0+2ip, r0+2ip+1
#pragma unroll
            for (int j = 0; j < 8; ++j) unpack2(acc2[ip][j], za[j], zb[j]);
#pragma unroll
            for (int lane = 0; lane < 2; ++lane) {
                const float* z = lane ? zb : za;
                int i = ip * 2 + lane;
                int b = r0 + i;
#pragma unroll
                for (int jj = 0; jj < 2; ++jj) {
                    float zi = z[jj * 4 + 0] + bias[jj][0];
                    float zj = z[jj * 4 + 1] + bias[jj][1];
                    float zf = z[jj * 4 + 2] + bias[jj][2];
                    float zo = z[jj * 4 + 3] + bias[jj][3];
                    float c2 = cst[i][jj] * sigf(zf) + sigf(zi) * tanh_fast(zj);
                    float h2 = tanh_fast(c2) * sigf(zo);
                    cst[i][jj] = c2;
                    Hst[b * 33 + j0 + jj] = h2;
                }
            }
        }
        __syncthreads();

        // ---- coalesced transposed writeback: g_h[l][t][p*32+j][b] ----
        for (int idx = tid; idx < 32 * 32; idx += 256) {
            int j = idx >> 5, bq = idx & 31;
            float4 v = make_float4(Hst[(bq * 4 + 0) * 33 + j],
                                   Hst[(bq * 4 + 1) * 33 + j],
                                   Hst[(bq * 4 + 2) * 33 + j],
                                   Hst[(bq * 4 + 3) * 33 + j]);
            *(float4*)&g_h[l][t][p * 32 + j][bq * 4] = v;
        }
        __threadfence();
        __syncthreads();
        if (tid == 0) atomicAdd(&g_flag[l * T + t], 1);
    }
}

// grid = T blocks x 128 threads: pred[b,t] + per-t partial loss
__global__ void pred_kernel(const float* __restrict__ labels,
                            const float* __restrict__ Wd,
                            const float* __restrict__ bd,
                            float* __restrict__ out, int out_size) {
    const int t = blockIdx.x;
    const int b = threadIdx.x;
    float s = 0.0f;
#pragma unroll
    for (int j = 0; j < H; ++j)
        s += g_h[L - 1][t][j][b] * Wd[t * H + j];
    s += bd[t];
    float pred = fmaxf(s, 0.0f);
    if (out_size >= B * T) out[b * T + t] = pred;
    float d = labels[b * T + t] - pred;
    d = d * d;
    __shared__ float red[128];
    red[b] = d;
    __syncthreads();
    for (int s2 = 64; s2 > 0; s2 >>= 1) {
        if (b < s2) red[b] += red[b + s2];
        __syncthreads();
    }
    if (b == 0) g_lpart[t] = red[0];
}

__global__ void loss_kernel(float* __restrict__ out, int out_size) {
    __shared__ float red[64];
    int tid = threadIdx.x;
    red[tid] = g_lpart[tid];
    __syncthreads();
    for (int s2 = 32; s2 > 0; s2 >>= 1) {
        if (tid < s2) red[tid] += red[tid + s2];
        __syncthreads();
    }
    if (tid == 0) {
        float loss = red[0] / (float)(B * T);
        if (out_size == B * T + 1) out[B * T] = loss;
        else if (out_size == 1) out[0] = loss;
    }
}

extern "C" void kernel_launch(void* const* d_in, const int* in_sizes, int n_in,
                              void* d_out, int out_size) {
    const float* x      = (const float*)d_in[0];
    const float* labels = (const float*)d_in[1];
    const float* W0     = (const float*)d_in[2];
    const float* b0     = (const float*)d_in[3];
    const float* Wl     = (const float*)d_in[4];
    const float* bl     = (const float*)d_in[5];
    const float* Wd     = (const float*)d_in[6];
    const float* bd     = (const float*)d_in[7];
    float* out = (float*)d_out;

    const int smem_bytes = 2 * KMAX * NCOLS * (int)sizeof(float);  // 128 KB
    cudaFuncSetAttribute(lstm_wavefront_kernel,
                         cudaFuncAttributeMaxDynamicSharedMemorySize, smem_bytes);

    reset_kernel<<<(L * T + 255) / 256, 256>>>();
    lstm_wavefront_kernel<<<L * NPART, 256, smem_bytes>>>(x, W0, b0, Wl, bl);
    pred_kernel<<<T, 128>>>(labels, Wd, bd, out, out_size);
    loss_kernel<<<1, 64>>>(out, out_size);
}